// round 15
// baseline (speedup 1.0000x reference)
#include <cuda_runtime.h>
#include <cuda_bf16.h>
#include <math.h>
#include <stdint.h>

#define NB 16
#define NT 2048
#define NC 1024
#define NH 64

// Q projection fp32; K/V pre-split bf16 (hi/lo) in MMA-ready layouts.
__device__ float    g_q[NB * NT * NH];
__device__ uint32_t g_kh4[NB * NT * (NH / 2)];          // [row][h-pair]
__device__ uint32_t g_kl4[NB * NT * (NH / 2)];
__device__ uint32_t g_vh4[NB * 32 * NH * 32];           // [b][tile][h][s-pair]
__device__ uint32_t g_vl4[NB * 32 * NH * 32];
// Pre-split weights, [n:192][k-pair:512] (cp.async-ready, row = 1024B)
__device__ uint32_t g_wh4[192 * 512];
__device__ uint32_t g_wl4[192 * 512];
// Dynamic work queue for the attention kernel (zeroed in split_w each launch)
__device__ int g_work_ctr;

__device__ __forceinline__ uint32_t pack_bf16(float a, float b) {
    __nv_bfloat162 t = __floats2bfloat162_rn(a, b);
    return *reinterpret_cast<uint32_t*>(&t);
}

// rn hi/lo split of a float pair
__device__ __forceinline__ void split_pair(float x0, float x1,
                                           uint32_t& hp, uint32_t& lp) {
    hp = pack_bf16(x0, x1);
    float h0 = __uint_as_float(hp << 16);
    float h1 = __uint_as_float(hp & 0xFFFF0000u);
    lp = pack_bf16(x0 - h0, x1 - h1);
}

__device__ __forceinline__ uint32_t smem_u32(const void* p) {
    uint32_t a;
    asm("{ .reg .u64 t; cvta.to.shared.u64 t, %1; cvt.u32.u64 %0, t; }"
        : "=r"(a) : "l"(p));
    return a;
}

__device__ __forceinline__ float ex2f(float x) {
    float r;
    asm("ex2.approx.ftz.f32 %0, %1;" : "=f"(r) : "f"(x));
    return r;
}

#define MMA_BF16(c, a0, a1, a2, a3, b0, b1)                                \
    asm volatile(                                                          \
        "mma.sync.aligned.m16n8k16.row.col.f32.bf16.bf16.f32 "             \
        "{%0,%1,%2,%3}, {%4,%5,%6,%7}, {%8,%9}, {%0,%1,%2,%3};"            \
        : "+f"((c)[0]), "+f"((c)[1]), "+f"((c)[2]), "+f"((c)[3])           \
        : "r"(a0), "r"(a1), "r"(a2), "r"(a3), "r"(b0), "r"(b1))

#define CP_ASYNC16(dst, src) \
    asm volatile("cp.async.cg.shared.global [%0], [%1], 16;" \
        :: "r"(dst), "l"(src) : "memory")
#define CP_COMMIT() asm volatile("cp.async.commit_group;" ::: "memory")
#define CP_WAIT0()  asm volatile("cp.async.wait_group 0;" ::: "memory")

// ===========================================================================
// Kernel 0: split weights -> bf16 hi/lo, [n][k] layout; reset work counter.
// ===========================================================================
__global__ __launch_bounds__(256) void split_w_kernel(
    const float* __restrict__ wq,
    const float* __restrict__ wk,
    const float* __restrict__ wv)
{
    if (blockIdx.x == 0 && threadIdx.x == 0) g_work_ctr = 0;
    const int n = blockIdx.x;          // 0..191
    const int seg = n >> 6;
    const int nc = n & 63;
    const float* wp = (seg == 0) ? wq : (seg == 1) ? wk : wv;
    for (int kp = threadIdx.x; kp < 512; kp += 256) {
        float v0 = wp[(size_t)(2 * kp) * NH + nc];
        float v1 = wp[(size_t)(2 * kp + 1) * NH + nc];
        uint32_t hp, lp;
        split_pair(v0, v1, hp, lp);
        g_wh4[n * 512 + kp] = hp;
        g_wl4[n * 512 + kp] = lp;
    }
}

// ===========================================================================
// Kernel 1: fused QKV projection. M=128, N=192 (single column!), grid 256.
// x streamed ONCE per 128-row block. 8 warps = 4(m) x 2(n); warp tile 32x96.
// Epilogue: Q fp32, K split bf16, V split bf16 transposed (smem bounce).
// ===========================================================================
#define WST 20                       // u32 stride per w row (16 used)
#define XRST 36                      // float stride per raw x row (32 used)
#define W_OFF 0
#define W_LO  3840                   // 192 * 20
#define W_BUF 7680                   // hi + lo
#define XRAW_OFF 15360               // 2 * W_BUF
#define XRAW_BUF 4608                // 128 * 36
#define QKV_SMEM_U32 (XRAW_OFF + 2 * XRAW_BUF)   // 24576 u32 = 98304 B
#define QKV_SMEM_BYTES (QKV_SMEM_U32 * 4)
#define VBST 65                      // vbuf fp32 stride (reuses XRAW region)

__global__ __launch_bounds__(256) void qkv_mma_kernel(
    const float* __restrict__ x)
{
    extern __shared__ char dynsm[];
    uint32_t* smu = reinterpret_cast<uint32_t*>(dynsm);
    float* smf = reinterpret_cast<float*>(dynsm);
    const uint32_t smbase = smem_u32(dynsm);

    const int tid = threadIdx.x;
    const int warp = tid >> 5;
    const int lane = tid & 31;
    const int g = lane >> 2;
    const int t4 = lane & 3;
    const int wm = warp & 3;
    const int wn = warp >> 2;
    const int m_base = wm * 32;
    const int n_base = wn * 96;
    const int row0 = blockIdx.x * 128;

    float acc[2][12][4];
#pragma unroll
    for (int mt = 0; mt < 2; mt++)
#pragma unroll
        for (int nt = 0; nt < 12; nt++)
#pragma unroll
            for (int i = 0; i < 4; i++) acc[mt][nt][i] = 0.f;

    // ---- cp.async one K-slab (w hi/lo + raw x) into buffer b ----
    auto issue_cp = [&](int b, int k0) {
        // w: 1536 chunks (192 rows x 4 c4 x 2 arrays)
#pragma unroll
        for (int it = 0; it < 6; it++) {
            int p = tid + it * 256;
            int lo = (p >= 768);
            int rem = p - lo * 768;
            int n_l = rem >> 2;
            int c4 = rem & 3;
            const uint32_t* src = (lo ? g_wl4 : g_wh4)
                + (size_t)n_l * 512 + (k0 >> 1) + c4 * 4;
            CP_ASYNC16(smbase + (W_OFF + b * W_BUF + lo * W_LO
                                 + n_l * WST + c4 * 4) * 4, src);
        }
        // x raw: 1024 chunks
#pragma unroll
        for (int it = 0; it < 4; it++) {
            int p = tid + it * 256;
            int r = p >> 3;
            int c4 = p & 7;
            const float* src = x + (size_t)(row0 + r) * NC + k0 + c4 * 4;
            CP_ASYNC16(smbase + (XRAW_OFF + b * XRAW_BUF
                                 + r * XRST + c4 * 4) * 4, src);
        }
        CP_COMMIT();
    };

    issue_cp(0, 0);

    const int NIT = NC / 32;   // 32
    for (int t = 0; t < NIT; t++) {
        const int b = t & 1;
        CP_WAIT0();
        __syncthreads();
        if (t + 1 < NIT) issue_cp(b ^ 1, (t + 1) * 32);

        const float* raw = smf + XRAW_OFF + b * XRAW_BUF;
        const uint32_t* Bh = smu + W_OFF + b * W_BUF;
        const uint32_t* Bl = Bh + W_LO;

#pragma unroll
        for (int ks = 0; ks < 2; ks++) {
            // A fragments for both mt (built once per ks)
            uint32_t ah[2][4], al[2][4];
#pragma unroll
            for (int mt = 0; mt < 2; mt++) {
                int r0 = m_base + mt * 16 + g;
                int c = ks * 16 + t4 * 2;
                float2 v00 = *reinterpret_cast<const float2*>(raw + r0 * XRST + c);
                float2 v10 = *reinterpret_cast<const float2*>(raw + (r0 + 8) * XRST + c);
                float2 v01 = *reinterpret_cast<const float2*>(raw + r0 * XRST + c + 8);
                float2 v11 = *reinterpret_cast<const float2*>(raw + (r0 + 8) * XRST + c + 8);
                split_pair(v00.x, v00.y, ah[mt][0], al[mt][0]);
                split_pair(v10.x, v10.y, ah[mt][1], al[mt][1]);
                split_pair(v01.x, v01.y, ah[mt][2], al[mt][2]);
                split_pair(v11.x, v11.y, ah[mt][3], al[mt][3]);
            }
#pragma unroll
            for (int nt = 0; nt < 12; nt++) {
                const uint32_t* bp = Bh + (n_base + nt * 8 + g) * WST + ks * 8 + t4;
                uint32_t bh0 = bp[0], bh1 = bp[4];
                const uint32_t* bp2 = Bl + (n_base + nt * 8 + g) * WST + ks * 8 + t4;
                uint32_t bl0 = bp2[0], bl1 = bp2[4];
#pragma unroll
                for (int mt = 0; mt < 2; mt++) {
                    MMA_BF16(acc[mt][nt], ah[mt][0], ah[mt][1], ah[mt][2], ah[mt][3], bh0, bh1);
                    MMA_BF16(acc[mt][nt], ah[mt][0], ah[mt][1], ah[mt][2], ah[mt][3], bl0, bl1);
                    MMA_BF16(acc[mt][nt], al[mt][0], al[mt][1], al[mt][2], al[mt][3], bh0, bh1);
                }
            }
        }
        __syncthreads();
    }

    // ---- epilogue: Q fp32 / K split / V to smem bounce ----
#pragma unroll
    for (int mt = 0; mt < 2; mt++) {
#pragma unroll
        for (int nt = 0; nt < 12; nt++) {
            int n_global = n_base + nt * 8 + t4 * 2;
            int r0 = m_base + mt * 16 + g;
            if (n_global < 64) {
                size_t gr = (size_t)row0 + r0;
                *reinterpret_cast<float2*>(&g_q[gr * NH + n_global]) =
                    make_float2(acc[mt][nt][0], acc[mt][nt][1]);
                *reinterpret_cast<float2*>(&g_q[(gr + 8) * NH + n_global]) =
                    make_float2(acc[mt][nt][2], acc[mt][nt][3]);
            } else if (n_global < 128) {
                int kc2 = (n_global - 64) >> 1;
                size_t gr = (size_t)row0 + r0;
                uint32_t hp, lp;
                split_pair(acc[mt][nt][0], acc[mt][nt][1], hp, lp);
                g_kh4[gr * 32 + kc2] = hp;
                g_kl4[gr * 32 + kc2] = lp;
                split_pair(acc[mt][nt][2], acc[mt][nt][3], hp, lp);
                g_kh4[(gr + 8) * 32 + kc2] = hp;
                g_kl4[(gr + 8) * 32 + kc2] = lp;
            }
        }
    }
    // V bounce: every CTA covers cols 128..191 (wn==1 warps, nt>=4)
    __syncthreads();   // main-loop smem reads done everywhere
    float* vbuf = smf + XRAW_OFF;   // [128][VBST] fp32
    if (wn == 1) {
#pragma unroll
        for (int mt = 0; mt < 2; mt++) {
#pragma unroll
            for (int nt = 4; nt < 12; nt++) {
                int n_global = n_base + nt * 8 + t4 * 2;   // 128..190
                int vc = n_global - 128;
                int r0 = m_base + mt * 16 + g;
                vbuf[r0 * VBST + vc] = acc[mt][nt][0];
                vbuf[r0 * VBST + vc + 1] = acc[mt][nt][1];
                vbuf[(r0 + 8) * VBST + vc] = acc[mt][nt][2];
                vbuf[(r0 + 8) * VBST + vc + 1] = acc[mt][nt][3];
            }
        }
    }
    __syncthreads();
    const int bb = row0 >> 11;
    const int st0 = (row0 & 2047) >> 6;
#pragma unroll
    for (int it = 0; it < 16; it++) {
        int idx = tid + it * 256;       // 0..4095
        int s2 = idx & 31;
        int rest = idx >> 5;
        int h = rest & 63;
        int sub = rest >> 6;            // 0..1
        float a = vbuf[(sub * 64 + 2 * s2) * VBST + h];
        float c = vbuf[(sub * 64 + 2 * s2 + 1) * VBST + h];
        uint32_t hp, lp;
        split_pair(a, c, hp, lp);
        size_t dst = ((size_t)(bb * 32 + st0 + sub) * NH + h) * 32 + s2;
        g_vh4[dst] = hp;
        g_vl4[dst] = lp;
    }
}

// ===========================================================================
// Kernel 2: causal flash attention, PERSISTENT with LPT work queue.
// Grid 148. Work item wi -> (qt = 15 - wi/16, b = wi%16): heaviest first.
// BM=128, BN=64, 8 warps. Pre-split K/V via cp.async in fragment layout.
// PV full 3-MMA split (R7-proven precision). Softmax base-2.
// ===========================================================================
#define AST 36                        // u32 stride per smem row (32 used)
#define KV_ARR 2304                   // 64 * 36
#define KV_BUF (4 * KV_ARR)           // kh, kl, vh, vl
#define ATTN_SMEM_U32 (2 * KV_BUF)    // 18432 u32 = 73728 B
#define ATTN_SMEM_BYTES (ATTN_SMEM_U32 * 4)
#define SC2 0.1803368801111204f       // 0.125 * log2(e)
#define N_ITEMS 256

__global__ __launch_bounds__(256) void attn_mma_kernel(float* __restrict__ out)
{
    extern __shared__ char dynsm[];
    uint32_t* smu = reinterpret_cast<uint32_t*>(dynsm);
    const uint32_t smbase = smem_u32(dynsm);
    __shared__ int s_wi;

    const int tid = threadIdx.x;
    const int warp = tid >> 5;
    const int lane = tid & 31;
    const int g = lane >> 2;
    const int t4 = lane & 3;
    const int m_base = warp * 16;

    for (;;) {
        if (tid == 0) s_wi = atomicAdd(&g_work_ctr, 1);
        __syncthreads();   // broadcasts s_wi; also fences prev item's smem reads
        const int wi = s_wi;
        if (wi >= N_ITEMS) return;
        const int qt = 15 - (wi >> 4);
        const int b = wi & 15;
        const int qs = qt * 128;
        const int ntiles = 2 * qt + 2;

        // ---- cp.async one pre-split KV tile into buffer ----
        auto issue_cp = [&](int buf, int st) {
#pragma unroll
            for (int it = 0; it < 8; it++) {
                int p = tid + it * 256;        // 0..2047
                int arr = p >> 9;              // 0:kh 1:kl 2:vh 3:vl
                int rem = p & 511;
                int r = rem >> 3;
                int c4 = rem & 7;
                const uint32_t* src;
                if (arr == 0)
                    src = g_kh4 + ((size_t)b * NT + st * 64 + r) * 32 + c4 * 4;
                else if (arr == 1)
                    src = g_kl4 + ((size_t)b * NT + st * 64 + r) * 32 + c4 * 4;
                else if (arr == 2)
                    src = g_vh4 + ((size_t)(b * 32 + st) * NH + r) * 32 + c4 * 4;
                else
                    src = g_vl4 + ((size_t)(b * 32 + st) * NH + r) * 32 + c4 * 4;
                CP_ASYNC16(smbase + (buf * KV_BUF + arr * KV_ARR
                                     + r * AST + c4 * 4) * 4, src);
            }
            CP_COMMIT();
        };

        issue_cp(0, 0);

        // ---- Q fragments straight from gmem (overlaps tile-0 cp) ----
        uint32_t qah[4][4], qal[4][4];
        {
            const float* qg = g_q + ((size_t)b * NT + qs) * NH;
            int r0 = m_base + g;
#pragma unroll
            for (int kc = 0; kc < 4; kc++) {
                int c = kc * 16 + t4 * 2;
                float2 v00 = *reinterpret_cast<const float2*>(qg + (size_t)r0 * NH + c);
                float2 v10 = *reinterpret_cast<const float2*>(qg + (size_t)(r0 + 8) * NH + c);
                float2 v01 = *reinterpret_cast<const float2*>(qg + (size_t)r0 * NH + c + 8);
                float2 v11 = *reinterpret_cast<const float2*>(qg + (size_t)(r0 + 8) * NH + c + 8);
                split_pair(v00.x, v00.y, qah[kc][0], qal[kc][0]);
                split_pair(v10.x, v10.y, qah[kc][1], qal[kc][1]);
                split_pair(v01.x, v01.y, qah[kc][2], qal[kc][2]);
                split_pair(v11.x, v11.y, qah[kc][3], qal[kc][3]);
            }
        }

        float m0 = -1e30f, m1 = -1e30f, l0 = 0.f, l1 = 0.f;
        float oacc[8][4];
#pragma unroll
        for (int nt = 0; nt < 8; nt++)
#pragma unroll
            for (int e = 0; e < 4; e++) oacc[nt][e] = 0.f;

        for (int st = 0; st < ntiles; st++) {
            const int s0 = st * 64;
            const int buf = st & 1;
            CP_WAIT0();
            __syncthreads();
            if (st + 1 < ntiles) issue_cp(buf ^ 1, st + 1);

            if (s0 > qs + m_base + 15) continue;   // fully masked for this warp

            const uint32_t* KH = smu + buf * KV_BUF;
            const uint32_t* KL = KH + KV_ARR;
            const uint32_t* VH = KH + 2 * KV_ARR;
            const uint32_t* VL = KH + 3 * KV_ARR;

            // ---- S = Q K^T (split bf16, 3 MMAs) ----
            float sacc[8][4];
#pragma unroll
            for (int nt = 0; nt < 8; nt++)
#pragma unroll
                for (int e = 0; e < 4; e++) sacc[nt][e] = 0.f;
#pragma unroll
            for (int kc = 0; kc < 4; kc++) {
#pragma unroll
                for (int nt = 0; nt < 8; nt++) {
                    const uint32_t* bp = KH + (nt * 8 + g) * AST + kc * 8 + t4;
                    uint32_t bh0 = bp[0], bh1 = bp[4];
                    const uint32_t* bp2 = KL + (nt * 8 + g) * AST + kc * 8 + t4;
                    uint32_t bl0 = bp2[0], bl1 = bp2[4];
                    MMA_BF16(sacc[nt], qah[kc][0], qah[kc][1], qah[kc][2], qah[kc][3], bh0, bh1);
                    MMA_BF16(sacc[nt], qah[kc][0], qah[kc][1], qah[kc][2], qah[kc][3], bl0, bl1);
                    MMA_BF16(sacc[nt], qal[kc][0], qal[kc][1], qal[kc][2], qal[kc][3], bh0, bh1);
                }
            }

            // ---- scale (base-2) + causal mask ----
            const bool maskzone = (s0 + 63 > qs + m_base);
            if (maskzone) {
#pragma unroll
                for (int nt = 0; nt < 8; nt++) {
#pragma unroll
                    for (int e = 0; e < 4; e++) {
                        int col = s0 + nt * 8 + 2 * t4 + (e & 1);
                        int row = qs + m_base + g + ((e >= 2) ? 8 : 0);
                        float v = sacc[nt][e] * SC2;
                        sacc[nt][e] = (col > row) ? -1e30f : v;
                    }
                }
            } else {
#pragma unroll
                for (int nt = 0; nt < 8; nt++)
#pragma unroll
                    for (int e = 0; e < 4; e++) sacc[nt][e] *= SC2;
            }

            // ---- online softmax (base-2), rows g and g+8 ----
            float mx0 = -1e30f, mx1 = -1e30f;
#pragma unroll
            for (int nt = 0; nt < 8; nt++) {
                mx0 = fmaxf(mx0, fmaxf(sacc[nt][0], sacc[nt][1]));
                mx1 = fmaxf(mx1, fmaxf(sacc[nt][2], sacc[nt][3]));
            }
            mx0 = fmaxf(mx0, __shfl_xor_sync(0xffffffffu, mx0, 1));
            mx0 = fmaxf(mx0, __shfl_xor_sync(0xffffffffu, mx0, 2));
            mx1 = fmaxf(mx1, __shfl_xor_sync(0xffffffffu, mx1, 1));
            mx1 = fmaxf(mx1, __shfl_xor_sync(0xffffffffu, mx1, 2));
            float nm0 = fmaxf(m0, mx0), nm1 = fmaxf(m1, mx1);
            float c0 = ex2f(m0 - nm0), c1 = ex2f(m1 - nm1);
            m0 = nm0; m1 = nm1;
            float sum0 = 0.f, sum1 = 0.f;
#pragma unroll
            for (int nt = 0; nt < 8; nt++) {
                float p0 = ex2f(sacc[nt][0] - nm0);
                float p1 = ex2f(sacc[nt][1] - nm0);
                float p2 = ex2f(sacc[nt][2] - nm1);
                float p3 = ex2f(sacc[nt][3] - nm1);
                sacc[nt][0] = p0; sacc[nt][1] = p1;
                sacc[nt][2] = p2; sacc[nt][3] = p3;
                sum0 += p0 + p1; sum1 += p2 + p3;
            }
            sum0 += __shfl_xor_sync(0xffffffffu, sum0, 1);
            sum0 += __shfl_xor_sync(0xffffffffu, sum0, 2);
            sum1 += __shfl_xor_sync(0xffffffffu, sum1, 1);
            sum1 += __shfl_xor_sync(0xffffffffu, sum1, 2);
            l0 = l0 * c0 + sum0;
            l1 = l1 * c1 + sum1;
#pragma unroll
            for (int nt = 0; nt < 8; nt++) {
                oacc[nt][0] *= c0; oacc[nt][1] *= c0;
                oacc[nt][2] *= c1; oacc[nt][3] *= c1;
            }

            // ---- O += P V (P split bf16: Ph*Vh + Ph*Vl + Pl*Vh) ----
#pragma unroll
            for (int kc = 0; kc < 4; kc++) {
                uint32_t pa0, pa1, pa2, pa3, pl0, pl1, pl2, pl3;
                split_pair(sacc[2 * kc][0], sacc[2 * kc][1], pa0, pl0);
                split_pair(sacc[2 * kc][2], sacc[2 * kc][3], pa1, pl1);
                split_pair(sacc[2 * kc + 1][0], sacc[2 * kc + 1][1], pa2, pl2);
                split_pair(sacc[2 * kc + 1][2], sacc[2 * kc + 1][3], pa3, pl3);
#pragma unroll
                for (int nt = 0; nt < 8; nt++) {
                    const uint32_t* vp = VH + (nt * 8 + g) * AST + kc * 8 + t4;
                    uint32_t vb0 = vp[0], vb1 = vp[4];
                    const uint32_t* vp2 = VL + (nt * 8 + g) * AST + kc * 8 + t4;
                    uint32_t vl0 = vp2[0], vl1 = vp2[4];
                    MMA_BF16(oacc[nt], pa0, pa1, pa2, pa3, vb0, vb1);
                    MMA_BF16(oacc[nt], pa0, pa1, pa2, pa3, vl0, vl1);
                    MMA_BF16(oacc[nt], pl0, pl1, pl2, pl3, vb0, vb1);
                }
            }
        }

        // ---- epilogue: out = O / l ----
        float inv0 = 1.0f / l0;
        float inv1 = 1.0f / l1;
        size_t row0 = (size_t)b * NT + qs + m_base + g;
        size_t row1 = row0 + 8;
#pragma unroll
        for (int nt = 0; nt < 8; nt++) {
            int col = nt * 8 + 2 * t4;
            *reinterpret_cast<float2*>(&out[row0 * NH + col]) =
                make_float2(oacc[nt][0] * inv0, oacc[nt][1] * inv0);
            *reinterpret_cast<float2*>(&out[row1 * NH + col]) =
                make_float2(oacc[nt][2] * inv1, oacc[nt][3] * inv1);
        }
    }
}

// ===========================================================================
extern "C" void kernel_launch(void* const* d_in, const int* in_sizes, int n_in,
                              void* d_out, int out_size)
{
    const float* x  = (const float*)d_in[0];
    const float* wq = (const float*)d_in[1];
    const float* wk = (const float*)d_in[2];
    const float* wv = (const float*)d_in[3];
    float* out = (float*)d_out;

    split_w_kernel<<<192, 256>>>(wq, wk, wv);

    cudaFuncSetAttribute(qkv_mma_kernel,
                         cudaFuncAttributeMaxDynamicSharedMemorySize,
                         QKV_SMEM_BYTES);
    qkv_mma_kernel<<<256, 256, QKV_SMEM_BYTES>>>(x);

    cudaFuncSetAttribute(attn_mma_kernel,
                         cudaFuncAttributeMaxDynamicSharedMemorySize,
                         ATTN_SMEM_BYTES);
    attn_mma_kernel<<<148, 256, ATTN_SMEM_BYTES>>>(out);
}